// round 4
// baseline (speedup 1.0000x reference)
#include <cuda_runtime.h>
#include <cstdint>

// ---------------------------------------------------------------------------
// Problem constants
// ---------------------------------------------------------------------------
#define B_   32
#define C_   256
#define NX   961
#define NZ   49
#define XT_LD  256
#define ZZ_LD  64
#define CAT_LD 992     // mult of 32: K-padding, zero-initialized
#define PS_LD  992
#define PZ_LD  64

#define BM 128
#define BN 128
#define BK 32
#define TILE_WORDS (128 * 32)             // 16 KB per operand buffer
#define SMEM_BYTES (4 * TILE_WORDS * 4)   // A0,B0,A1,B1 = 64 KB

// ---------------------------------------------------------------------------
// Scratch (device globals; zero-initialized, never freed)
// ---------------------------------------------------------------------------
__device__ float g_XT [(size_t)B_ * NX * XT_LD];     // xf_trans^T [B][Nx][C] (tf32)
__device__ float g_ZZ [(size_t)B_ * 512 * ZZ_LD];    // [zf_trans; zf_g] [B][512][64] (tf32)
__device__ float g_CAT[(size_t)B_ * 768 * CAT_LD];   // [emb|self|xg] [B][3C][992] (tf32)
__device__ float g_PS [(size_t)B_ * NX * PS_LD];     // self probs (tf32)
__device__ float g_PZ [(size_t)B_ * NX * PZ_LD];     // cross probs (tf32)
__device__ float g_WR [393216];                      // rounded [Wq|Ws|Wg|Wfi]

// ---------------------------------------------------------------------------
__device__ __forceinline__ uint32_t cvt_tf32(float f) {
    uint32_t r;
    asm("cvt.rna.tf32.f32 %0, %1;" : "=r"(r) : "f"(f));
    return r;
}
__device__ __forceinline__ float round_tf32f(float f) {
    return __uint_as_float(cvt_tf32(f));
}
__device__ __forceinline__ uint32_t smem_u32(const void* p) {
    uint32_t a;
    asm("{ .reg .u64 t; cvta.to.shared.u64 t, %1; cvt.u32.u64 %0, t; }" : "=r"(a) : "l"(p));
    return a;
}
__device__ __forceinline__ void cp16(uint32_t dst, const float* src, int ss) {
    asm volatile("cp.async.cg.shared.global [%0], [%1], 16, %2;"
                 :: "r"(dst), "l"(src), "r"(ss));
}
#define CP_COMMIT() asm volatile("cp.async.commit_group;" ::: "memory")
#define CP_WAIT0()  asm volatile("cp.async.wait_group 0;" ::: "memory")

__device__ __forceinline__ void mma_tf32(float* d, const uint32_t* a, const uint32_t* b) {
    asm volatile(
        "mma.sync.aligned.m16n8k8.row.col.f32.tf32.tf32.f32 "
        "{%0,%1,%2,%3}, {%4,%5,%6,%7}, {%8,%9}, {%0,%1,%2,%3};"
        : "+f"(d[0]), "+f"(d[1]), "+f"(d[2]), "+f"(d[3])
        : "r"(a[0]), "r"(a[1]), "r"(a[2]), "r"(a[3]), "r"(b[0]), "r"(b[1]));
}

// XOR-swizzled word offset inside a [128 x 32] tile (16B-unit swizzle)
__device__ __forceinline__ int woff(int row, int col) {
    return (row << 5) + ((((col >> 2) ^ (row & 7)) << 2) | (col & 3));
}

// ---------------------------------------------------------------------------
// Staging. MODE 0: cp.async row-major-k (src pre-rounded tf32, ld mult of 32,
//                  k-tile always within ld; row-predicated zero-fill)
//         MODE 1: transpose float4 (src tf32, ld mult of 4), src[k][n]
//         MODE 2: transpose scalar + cvt (raw fp32, any ld), src[k][n]
// ---------------------------------------------------------------------------
template<int MODE>
__device__ __forceinline__ void stage(uint32_t sbyte, uint32_t* sw,
                                      const float* __restrict__ src, int ld,
                                      int r0, int rmax, int k0, int t)
{
    if (MODE == 0) {
#pragma unroll
        for (int i = 0; i < 4; i++) {
            int q = i * 256 + t;
            int row = q >> 3, u = q & 7;
            int ok = (r0 + row < rmax);
            const float* s = ok ? (src + (size_t)(r0 + row) * ld + k0 + u * 4) : src;
            uint32_t d = sbyte + (uint32_t)(((row << 5) + ((u ^ (row & 7)) << 2)) * 4);
            cp16(d, s, ok ? 16 : 0);
        }
    } else if (MODE == 1) {
#pragma unroll
        for (int i = 0; i < 4; i++) {
            int q = i * 256 + t;
            int kk = q >> 5, c = q & 31;
            int n = r0 + c * 4;
            float4 v = make_float4(0.f, 0.f, 0.f, 0.f);
            const float* s = src + (size_t)(k0 + kk) * ld + n;
            if (n + 3 < rmax) {
                v = *reinterpret_cast<const float4*>(s);
            } else if (n < rmax) {
                v.x = s[0];
                if (n + 1 < rmax) v.y = s[1];
                if (n + 2 < rmax) v.z = s[2];
            }
            int lr = c * 4;
            sw[woff(lr + 0, kk)] = __float_as_uint(v.x);
            sw[woff(lr + 1, kk)] = __float_as_uint(v.y);
            sw[woff(lr + 2, kk)] = __float_as_uint(v.z);
            sw[woff(lr + 3, kk)] = __float_as_uint(v.w);
        }
    } else {
#pragma unroll
        for (int i = 0; i < 16; i++) {
            int q = i * 256 + t;
            int lr = q & 127, kk = q >> 7;
            float v = 0.f;
            if (r0 + lr < rmax) v = src[(size_t)(k0 + kk) * ld + r0 + lr];
            sw[woff(lr, kk)] = cvt_tf32(v);
        }
    }
}

// ---------------------------------------------------------------------------
// tf32 GEMM: D[m][n] = epi( sum_k A[m][k] * B[n][k] )
// EPI 0: + bias[col]         EPI 1: relu(bn per row)    EPI 2: plain
// EPI 4: stacked Z — row<256: +bias[row]; row>=256: relu(bn) with bias2/bn[row-256]
// ---------------------------------------------------------------------------
template<int LA, int LB, int EPI, bool ROUND>
__global__ void __launch_bounds__(256, 2) mm(
    const float* __restrict__ A, const float* __restrict__ Bm, float* __restrict__ D,
    const float* __restrict__ bias, const float* __restrict__ bias2,
    const float* __restrict__ gamma, const float* __restrict__ beta,
    const float* __restrict__ mean, const float* __restrict__ var,
    int M, int N, int K, int lda, int ldb, int ldd,
    long abs_, long bbs_, long dbs_)
{
    extern __shared__ uint32_t smem[];
    const uint32_t sbyte = smem_u32(smem);

    const int t = threadIdx.x;
    const int wid = t >> 5, lane = t & 31;
    const int warp_m = wid & 3, warp_n = wid >> 2;
    const int qid = lane >> 2, qtid = lane & 3;
    const int b = blockIdx.z;
    const int n0 = blockIdx.x * BN;
    const int m0 = blockIdx.y * BM;

    const float* Ab = A + (long)b * abs_;
    const float* Bb = Bm + (long)b * bbs_;
    float* Db = D + (long)b * dbs_;

    float acc[2][8][4];
#pragma unroll
    for (int i = 0; i < 2; i++)
#pragma unroll
        for (int j = 0; j < 8; j++)
#pragma unroll
            for (int k = 0; k < 4; k++) acc[i][j][k] = 0.f;

    const int T = (K + BK - 1) / BK;

    // buffer layout: A0 @0, B0 @TILE, A1 @2*TILE, B1 @3*TILE (words)
    stage<LA>(sbyte, smem, Ab, lda, m0, M, 0, t);
    stage<LB>(sbyte + TILE_WORDS * 4, smem + TILE_WORDS, Bb, ldb, n0, N, 0, t);
    CP_COMMIT();
    CP_WAIT0();
    __syncthreads();

    for (int tt = 0; tt < T; tt++) {
        const int cur = (tt & 1) * 2 * TILE_WORDS;
        if (tt + 1 < T) {
            const int nxt = ((tt + 1) & 1) * 2 * TILE_WORDS;
            stage<LA>(sbyte + nxt * 4, smem + nxt, Ab, lda, m0, M, (tt + 1) * BK, t);
            stage<LB>(sbyte + (nxt + TILE_WORDS) * 4, smem + nxt + TILE_WORDS,
                      Bb, ldb, n0, N, (tt + 1) * BK, t);
            CP_COMMIT();
        }
        const uint32_t* Ac = smem + cur;
        const uint32_t* Bc = smem + cur + TILE_WORDS;
#pragma unroll
        for (int ks = 0; ks < 4; ks++) {
            const int kk = ks * 8;
            uint32_t afr[2][4];
#pragma unroll
            for (int im = 0; im < 2; im++) {
                int R = warp_m * 32 + im * 16 + qid;
                afr[im][0] = Ac[woff(R,     kk + qtid)];
                afr[im][1] = Ac[woff(R + 8, kk + qtid)];
                afr[im][2] = Ac[woff(R,     kk + qtid + 4)];
                afr[im][3] = Ac[woff(R + 8, kk + qtid + 4)];
            }
            uint32_t bfr[8][2];
#pragma unroll
            for (int jn = 0; jn < 8; jn++) {
                int R = warp_n * 64 + jn * 8 + qid;
                bfr[jn][0] = Bc[woff(R, kk + qtid)];
                bfr[jn][1] = Bc[woff(R, kk + qtid + 4)];
            }
#pragma unroll
            for (int im = 0; im < 2; im++)
#pragma unroll
                for (int jn = 0; jn < 8; jn++)
                    mma_tf32(acc[im][jn], afr[im], bfr[jn]);
        }
        CP_WAIT0();
        __syncthreads();
    }

    // ---- epilogue ----
    const int mb = m0 + warp_m * 32;
    const int nb = n0 + warp_n * 64;

    float scl[2][2], sft[2][2];
    if (EPI == 1 || EPI == 4) {
#pragma unroll
        for (int im = 0; im < 2; im++)
#pragma unroll
            for (int h = 0; h < 2; h++) {
                int r = mb + im * 16 + qid + h * 8;
                if (EPI == 1) {
                    int ri = (r < M) ? r : 0;
                    float inv = rsqrtf(var[ri] + 1e-5f);
                    float s = gamma[ri] * inv;
                    scl[im][h] = s;
                    sft[im][h] = (bias[ri] - mean[ri]) * s + beta[ri];
                } else { // EPI 4
                    if (r < 256) {
                        scl[im][h] = 1.f;
                        sft[im][h] = bias[r];
                    } else {
                        int ri = (r < M) ? (r - 256) : 0;
                        float inv = rsqrtf(var[ri] + 1e-5f);
                        float s = gamma[ri] * inv;
                        scl[im][h] = s;
                        sft[im][h] = (bias2[ri] - mean[ri]) * s + beta[ri];
                    }
                }
            }
    }

#pragma unroll
    for (int im = 0; im < 2; im++) {
#pragma unroll
        for (int jn = 0; jn < 8; jn++) {
            int c0 = nb + jn * 8 + 2 * qtid;
#pragma unroll
            for (int h = 0; h < 2; h++) {
                int r = mb + im * 16 + qid + h * 8;
                if (r >= M) continue;
                float v0 = acc[im][jn][h * 2 + 0];
                float v1 = acc[im][jn][h * 2 + 1];
                if (EPI == 0) {
                    if (c0 < N)     v0 += bias[c0];
                    if (c0 + 1 < N) v1 += bias[c0 + 1];
                }
                if (EPI == 1) {
                    v0 = fmaxf(v0 * scl[im][h] + sft[im][h], 0.f);
                    v1 = fmaxf(v1 * scl[im][h] + sft[im][h], 0.f);
                }
                if (EPI == 4) {
                    v0 = v0 * scl[im][h] + sft[im][h];
                    v1 = v1 * scl[im][h] + sft[im][h];
                    if (r >= 256) { v0 = fmaxf(v0, 0.f); v1 = fmaxf(v1, 0.f); }
                }
                if (ROUND) { v0 = round_tf32f(v0); v1 = round_tf32f(v1); }
                if (c0 < N)     Db[(long)r * ldd + c0]     = v0;
                if (c0 + 1 < N) Db[(long)r * ldd + c0 + 1] = v1;
            }
        }
    }
}

// ---------------------------------------------------------------------------
// Row softmax (row length M <= 1024, padded stride ld); stores tf32-rounded.
// ---------------------------------------------------------------------------
__global__ void softmax_rows(float* __restrict__ L, int M, int ld)
{
    float* p = L + (size_t)blockIdx.x * ld;
    const int t = threadIdx.x;

    float r[4];
    float mx = -1e30f;
#pragma unroll
    for (int i = 0; i < 4; i++) {
        int idx = t + i * 256;
        r[i] = (idx < M) ? p[idx] : -1e30f;
        mx = fmaxf(mx, r[i]);
    }
#pragma unroll
    for (int off = 16; off; off >>= 1)
        mx = fmaxf(mx, __shfl_xor_sync(0xffffffffu, mx, off));

    __shared__ float redmax[8];
    __shared__ float redsum[8];
    if ((t & 31) == 0) redmax[t >> 5] = mx;
    __syncthreads();
    mx = redmax[0];
#pragma unroll
    for (int w = 1; w < 8; w++) mx = fmaxf(mx, redmax[w]);

    float s = 0.f;
#pragma unroll
    for (int i = 0; i < 4; i++) {
        int idx = t + i * 256;
        r[i] = (idx < M) ? __expf(r[i] - mx) : 0.f;
        s += r[i];
    }
#pragma unroll
    for (int off = 16; off; off >>= 1)
        s += __shfl_xor_sync(0xffffffffu, s, off);
    if ((t & 31) == 0) redsum[t >> 5] = s;
    __syncthreads();
    s = 0.f;
#pragma unroll
    for (int w = 0; w < 8; w++) s += redsum[w];

    float inv = 1.f / s;
#pragma unroll
    for (int i = 0; i < 4; i++) {
        int idx = t + i * 256;
        if (idx < M) p[idx] = round_tf32f(r[i] * inv);
    }
}

// ---------------------------------------------------------------------------
// Pre-round the four weight matrices into g_WR: [Wq|Ws|Wg|Wfi]
// ---------------------------------------------------------------------------
__global__ void round_weights(const float* __restrict__ wq, const float* __restrict__ ws,
                              const float* __restrict__ wg, const float* __restrict__ wfi,
                              float* __restrict__ o)
{
    for (int i = blockIdx.x * 256 + threadIdx.x; i < 393216; i += gridDim.x * 256) {
        float v;
        if      (i < 65536)  v = wq [i];
        else if (i < 131072) v = ws [i - 65536];
        else if (i < 196608) v = wg [i - 131072];
        else                 v = wfi[i - 196608];
        o[i] = round_tf32f(v);
    }
}

// ---------------------------------------------------------------------------
extern "C" void kernel_launch(void* const* d_in, const int* in_sizes, int n_in,
                              void* d_out, int out_size)
{
    const float* zf  = (const float*)d_in[0];
    const float* xf  = (const float*)d_in[1];
    const float* Wq  = (const float*)d_in[2];
    const float* bq  = (const float*)d_in[3];
    const float* Ws_ = (const float*)d_in[4];
    const float* bs  = (const float*)d_in[5];
    const float* Wg  = (const float*)d_in[6];
    const float* bg  = (const float*)d_in[7];
    const float* g_gamma = (const float*)d_in[8];
    const float* g_beta  = (const float*)d_in[9];
    const float* g_mean  = (const float*)d_in[10];
    const float* g_var   = (const float*)d_in[11];
    const float* Wfi = (const float*)d_in[12];
    const float* bfi = (const float*)d_in[13];
    const float* fi_gamma = (const float*)d_in[14];
    const float* fi_beta  = (const float*)d_in[15];
    const float* fi_mean  = (const float*)d_in[16];
    const float* fi_var   = (const float*)d_in[17];
    float* out = (float*)d_out;

    float *XT, *ZZ, *CAT, *PS, *PZ, *WR;
    cudaGetSymbolAddress((void**)&XT,  g_XT);
    cudaGetSymbolAddress((void**)&ZZ,  g_ZZ);
    cudaGetSymbolAddress((void**)&CAT, g_CAT);
    cudaGetSymbolAddress((void**)&PS,  g_PS);
    cudaGetSymbolAddress((void**)&PZ,  g_PZ);
    cudaGetSymbolAddress((void**)&WR,  g_WR);

    cudaFuncSetAttribute(mm<2,0,0,true >, cudaFuncAttributeMaxDynamicSharedMemorySize, SMEM_BYTES);
    cudaFuncSetAttribute(mm<0,2,4,true >, cudaFuncAttributeMaxDynamicSharedMemorySize, SMEM_BYTES);
    cudaFuncSetAttribute(mm<0,2,1,true >, cudaFuncAttributeMaxDynamicSharedMemorySize, SMEM_BYTES);
    cudaFuncSetAttribute(mm<0,0,2,false>, cudaFuncAttributeMaxDynamicSharedMemorySize, SMEM_BYTES);
    cudaFuncSetAttribute(mm<0,1,2,false>, cudaFuncAttributeMaxDynamicSharedMemorySize, SMEM_BYTES);
    cudaFuncSetAttribute(mm<0,0,2,true >, cudaFuncAttributeMaxDynamicSharedMemorySize, SMEM_BYTES);
    cudaFuncSetAttribute(mm<0,1,1,false>, cudaFuncAttributeMaxDynamicSharedMemorySize, SMEM_BYTES);

    const long CNX = (long)C_ * NX;
    const long CNZ = (long)C_ * NZ;
    const long XT_BS  = (long)NX * XT_LD;
    const long ZZ_BS  = (long)512 * ZZ_LD;
    const long CAT_BS = (long)768 * CAT_LD;
    const long PS_BS  = (long)NX * PS_LD;
    const long PZ_BS  = (long)NX * PZ_LD;
    const long OUT_BS = (long)256 * NX;
    float* XG  = CAT + (long)512 * CAT_LD;   // xf_g rows
    float* SE  = CAT + (long)256 * CAT_LD;   // self_emb rows
    float* ZGp = ZZ + 256 * ZZ_LD;           // zf_g rows

    // 0) round weights -> WR
    round_weights<<<256, 256>>>(Wq, Ws_, Wg, Wfi, WR);

    // 1) XT[Nx,C] = xf^T @ Wq^T + bq       (A: xf transpose+cvt, B: WR cp.async)
    mm<2,0,0,true><<<dim3(2, 8, B_), 256, SMEM_BYTES>>>(
        xf, WR, XT, bq, nullptr, nullptr, nullptr, nullptr, nullptr,
        NX, 256, 256, NX, 256, XT_LD, CNX, 0, XT_BS);
    // 2) ZZ[512,Nz] = [Ws;Wg] @ zf  (rows<256: +bs; rows>=256: relu(bn, bg))
    mm<0,2,4,true><<<dim3(1, 4, B_), 256, SMEM_BYTES>>>(
        WR + 65536, zf, ZZ, bs, bg, g_gamma, g_beta, g_mean, g_var,
        512, NZ, 256, 256, NZ, ZZ_LD, 0, CNZ, ZZ_BS);
    // 3) XG[C,Nx] = relu(bn(Wg @ xf))      -> CAT rows [512,768)
    mm<0,2,1,true><<<dim3(8, 2, B_), 256, SMEM_BYTES>>>(
        WR + 131072, xf, XG, bg, nullptr, g_gamma, g_beta, g_mean, g_var,
        256, NX, 256, 256, NX, CAT_LD, 0, CNX, CAT_BS);
    // 4) PS[Nx,Nx] = XT @ XT^T
    mm<0,0,2,false><<<dim3(8, 8, B_), 256, SMEM_BYTES>>>(
        XT, XT, PS, nullptr, nullptr, nullptr, nullptr, nullptr, nullptr,
        NX, NX, 256, XT_LD, XT_LD, PS_LD, XT_BS, XT_BS, PS_BS);
    // 5) PZ[Nx,Nz] = XT @ zf_trans^T       (B: transpose-f4 from ZZ rows 0-255)
    mm<0,1,2,false><<<dim3(1, 8, B_), 256, SMEM_BYTES>>>(
        XT, ZZ, PZ, nullptr, nullptr, nullptr, nullptr, nullptr, nullptr,
        NX, NZ, 256, XT_LD, ZZ_LD, PZ_LD, XT_BS, ZZ_BS, PZ_BS);
    // 6) softmax
    softmax_rows<<<dim3(B_ * NX), 256>>>(PS, NX, PS_LD);
    softmax_rows<<<dim3(B_ * NX), 256>>>(PZ, NZ, PZ_LD);
    // 7) self_emb[C,Nx] = XG @ PS^T        (K padded to 992, padding is zero)
    mm<0,0,2,true><<<dim3(8, 2, B_), 256, SMEM_BYTES>>>(
        XG, PS, SE, nullptr, nullptr, nullptr, nullptr, nullptr, nullptr,
        256, NX, 992, CAT_LD, PS_LD, CAT_LD, CAT_BS, PS_BS, CAT_BS);
    // 8) emb[C,Nx] = zf_g @ PZ^T           (K padded to 64)
    mm<0,0,2,true><<<dim3(8, 2, B_), 256, SMEM_BYTES>>>(
        ZGp, PZ, CAT, nullptr, nullptr, nullptr, nullptr, nullptr, nullptr,
        256, NX, 64, ZZ_LD, PZ_LD, CAT_LD, ZZ_BS, PZ_BS, CAT_BS);
    // 9) out[O,Nx] = relu(bn(Wfi @ CAT))   (B: transpose-f4 from CAT)
    mm<0,1,1,false><<<dim3(8, 2, B_), 256, SMEM_BYTES>>>(
        WR + 196608, CAT, out, bfi, nullptr, fi_gamma, fi_beta, fi_mean, fi_var,
        256, NX, 768, 768, CAT_LD, NX, 0, CAT_BS, OUT_BS);
}

// round 5
// speedup vs baseline: 1.2563x; 1.2563x over previous
#include <cuda_runtime.h>
#include <cstdint>

// ---------------------------------------------------------------------------
// Problem constants
// ---------------------------------------------------------------------------
#define B_   32
#define C_   256
#define NX   961
#define NZ   49
#define XT_LD  256
#define ZZ_LD  64
#define CT_LD  768      // CATT row stride (mult of 32)
#define CT_ROWS 992     // CATT rows padded (zero rows 961..991)
#define PS_LD  992
#define PZ_LD  64

#define BM 128
#define BN 128
#define BK 32
#define TILE_WORDS (128 * 32)             // 16 KB per operand buffer
#define SMEM_BYTES (4 * TILE_WORDS * 4)   // A0,B0,A1,B1 = 64 KB

// ---------------------------------------------------------------------------
// Scratch (device globals; zero-initialized, never freed)
// ---------------------------------------------------------------------------
__device__ float g_XF [(size_t)B_ * NX * 256];        // xf^T   [B][Nx][C] (tf32)
__device__ float g_XT [(size_t)B_ * NX * XT_LD];      // xf_trans^T [B][Nx][C] (tf32)
__device__ float g_ZZ [(size_t)B_ * 512 * ZZ_LD];     // [zf_g; zf_trans] [B][512][64]
__device__ float g_CT [(size_t)B_ * CT_ROWS * CT_LD]; // [emb|self|xg] n-major [B][992][768]
__device__ float g_PS [(size_t)B_ * NX * PS_LD];      // self probs (tf32)
__device__ float g_PZ [(size_t)B_ * NX * PZ_LD];      // cross probs (tf32)
__device__ float g_WR [393216];                       // rounded [Wq|Wg|Ws|Wfi]

// ---------------------------------------------------------------------------
__device__ __forceinline__ uint32_t cvt_tf32(float f) {
    uint32_t r;
    asm("cvt.rna.tf32.f32 %0, %1;" : "=r"(r) : "f"(f));
    return r;
}
__device__ __forceinline__ float round_tf32f(float f) {
    return __uint_as_float(cvt_tf32(f));
}
__device__ __forceinline__ uint32_t smem_u32(const void* p) {
    uint32_t a;
    asm("{ .reg .u64 t; cvta.to.shared.u64 t, %1; cvt.u32.u64 %0, t; }" : "=r"(a) : "l"(p));
    return a;
}
__device__ __forceinline__ void cp16(uint32_t dst, const float* src, int ss) {
    asm volatile("cp.async.cg.shared.global [%0], [%1], 16, %2;"
                 :: "r"(dst), "l"(src), "r"(ss));
}
#define CP_COMMIT() asm volatile("cp.async.commit_group;" ::: "memory")
#define CP_WAIT0()  asm volatile("cp.async.wait_group 0;" ::: "memory")

__device__ __forceinline__ void mma_tf32(float* d, const uint32_t* a, const uint32_t* b) {
    asm volatile(
        "mma.sync.aligned.m16n8k8.row.col.f32.tf32.tf32.f32 "
        "{%0,%1,%2,%3}, {%4,%5,%6,%7}, {%8,%9}, {%0,%1,%2,%3};"
        : "+f"(d[0]), "+f"(d[1]), "+f"(d[2]), "+f"(d[3])
        : "r"(a[0]), "r"(a[1]), "r"(a[2]), "r"(a[3]), "r"(b[0]), "r"(b[1]));
}

// XOR-swizzled word offset inside a [128 x 32] tile
__device__ __forceinline__ int woff(int row, int col) {
    return (row << 5) + ((((col >> 2) ^ (row & 7)) << 2) | (col & 3));
}

// ---------------------------------------------------------------------------
// Staging.
// MODE 0: cp.async, src row-major-k (tf32, ld mult of 32, k-tile within row)
// MODE 1: transpose, src[k][n] tf32. Per thread: 4 stride-ld scalar loads
//         (lane-coalesced in n), one STS.128 — conflict-free.
// MODE 2: transpose scalar + cvt (raw fp32, any ld) — cold paths only.
// ---------------------------------------------------------------------------
template<int MODE>
__device__ __forceinline__ void stage(uint32_t sbyte, uint32_t* sw,
                                      const float* __restrict__ src, int ld,
                                      int r0, int rmax, int k0, int t)
{
    if (MODE == 0) {
#pragma unroll
        for (int i = 0; i < 4; i++) {
            int q = i * 256 + t;
            int row = q >> 3, u = q & 7;
            int ok = (r0 + row < rmax);
            const float* s = ok ? (src + (size_t)(r0 + row) * ld + k0 + u * 4) : src;
            uint32_t d = sbyte + (uint32_t)(((row << 5) + ((u ^ (row & 7)) << 2)) * 4);
            cp16(d, s, ok ? 16 : 0);
        }
    } else if (MODE == 1) {
#pragma unroll
        for (int i = 0; i < 4; i++) {
            int q = i * 256 + t;
            int lr = q & 127, g = q >> 7;   // row in tile, 16B k-group
            int n = r0 + lr;
            uint4 w = make_uint4(0u, 0u, 0u, 0u);
            if (n < rmax) {
                const float* s = src + (size_t)(k0 + g * 4) * ld + n;
                w.x = __float_as_uint(s[0]);
                w.y = __float_as_uint(s[(size_t)ld]);
                w.z = __float_as_uint(s[(size_t)2 * ld]);
                w.w = __float_as_uint(s[(size_t)3 * ld]);
            }
            *reinterpret_cast<uint4*>(sw + (lr << 5) + (((g ^ (lr & 7)) << 2))) = w;
        }
    } else {
#pragma unroll
        for (int i = 0; i < 16; i++) {
            int q = i * 256 + t;
            int lr = q & 127, kk = q >> 7;
            float v = 0.f;
            if (r0 + lr < rmax) v = src[(size_t)(k0 + kk) * ld + r0 + lr];
            sw[woff(lr, kk)] = cvt_tf32(v);
        }
    }
}

// ---------------------------------------------------------------------------
// tf32 GEMM: D[m][n] = epi( sum_k A[m][k] * B[n][k] )
// EPI 1: relu(bn per row m)
// EPI 2: plain
// EPI 4: Z-stack rows: r<256 relu(bn[r], bias) ; r>=256 +bias2[r-256]
// EPI 5: col split: c<256 +bias[c] -> D ; c>=256 relu(bn[c-256], bias2) -> D2(ld 768)
// ---------------------------------------------------------------------------
template<int LA, int LB, int EPI, bool ROUND>
__global__ void __launch_bounds__(256, 2) mm(
    const float* __restrict__ A, const float* __restrict__ Bm,
    float* __restrict__ D, float* __restrict__ D2,
    const float* __restrict__ bias, const float* __restrict__ bias2,
    const float* __restrict__ gamma, const float* __restrict__ beta,
    const float* __restrict__ mean, const float* __restrict__ var,
    int M, int N, int K, int lda, int ldb, int ldd,
    long abs_, long bbs_, long dbs_, long d2bs_)
{
    extern __shared__ uint32_t smem[];
    const uint32_t sbyte = smem_u32(smem);

    const int t = threadIdx.x;
    const int wid = t >> 5, lane = t & 31;
    const int warp_m = wid & 3, warp_n = wid >> 2;
    const int qid = lane >> 2, qtid = lane & 3;
    const int b = blockIdx.z;
    const int n0 = blockIdx.x * BN;
    const int m0 = blockIdx.y * BM;

    const float* Ab = A + (long)b * abs_;
    const float* Bb = Bm + (long)b * bbs_;
    float* Db = D + (long)b * dbs_;

    float acc[2][8][4];
#pragma unroll
    for (int i = 0; i < 2; i++)
#pragma unroll
        for (int j = 0; j < 8; j++)
#pragma unroll
            for (int k = 0; k < 4; k++) acc[i][j][k] = 0.f;

    // precomputed fragment word-index bases (all rows have row&7 == qid)
    int ko[8];
#pragma unroll
    for (int c4 = 0; c4 < 8; c4++) ko[c4] = ((c4 ^ qid) << 2);
    int arow[2], brow[8];
#pragma unroll
    for (int im = 0; im < 2; im++)
        arow[im] = ((warp_m * 32 + im * 16 + qid) << 5) + qtid;
#pragma unroll
    for (int jn = 0; jn < 8; jn++)
        brow[jn] = ((warp_n * 64 + jn * 8 + qid) << 5) + qtid;

    const int T = (K + BK - 1) / BK;

    stage<LA>(sbyte, smem, Ab, lda, m0, M, 0, t);
    stage<LB>(sbyte + TILE_WORDS * 4, smem + TILE_WORDS, Bb, ldb, n0, N, 0, t);
    CP_COMMIT();
    CP_WAIT0();
    __syncthreads();

    for (int tt = 0; tt < T; tt++) {
        const int cur = (tt & 1) * 2 * TILE_WORDS;
        if (tt + 1 < T) {
            const int nxt = ((tt + 1) & 1) * 2 * TILE_WORDS;
            stage<LA>(sbyte + nxt * 4, smem + nxt, Ab, lda, m0, M, (tt + 1) * BK, t);
            stage<LB>(sbyte + (nxt + TILE_WORDS) * 4, smem + nxt + TILE_WORDS,
                      Bb, ldb, n0, N, (tt + 1) * BK, t);
            CP_COMMIT();
        }
        const uint32_t* Ac = smem + cur;
        const uint32_t* Bc = smem + cur + TILE_WORDS;
#pragma unroll
        for (int ks = 0; ks < 4; ks++) {
            const int k0w = ko[2 * ks], k1w = ko[2 * ks + 1];
            uint32_t afr[2][4];
#pragma unroll
            for (int im = 0; im < 2; im++) {
                afr[im][0] = Ac[arow[im] + k0w];
                afr[im][1] = Ac[arow[im] + 256 + k0w];
                afr[im][2] = Ac[arow[im] + k1w];
                afr[im][3] = Ac[arow[im] + 256 + k1w];
            }
            uint32_t bfr[8][2];
#pragma unroll
            for (int jn = 0; jn < 8; jn++) {
                bfr[jn][0] = Bc[brow[jn] + k0w];
                bfr[jn][1] = Bc[brow[jn] + k1w];
            }
#pragma unroll
            for (int im = 0; im < 2; im++)
#pragma unroll
                for (int jn = 0; jn < 8; jn++)
                    mma_tf32(acc[im][jn], afr[im], bfr[jn]);
        }
        CP_WAIT0();
        __syncthreads();
    }

    // ---- epilogue ----
    const int mb = m0 + warp_m * 32;
    const int nb = n0 + warp_n * 64;

    float scl[2][2], sft[2][2];
    if (EPI == 1 || EPI == 4) {
#pragma unroll
        for (int im = 0; im < 2; im++)
#pragma unroll
            for (int h = 0; h < 2; h++) {
                int r = mb + im * 16 + qid + h * 8;
                if (EPI == 1) {
                    int ri = (r < M) ? r : 0;
                    float inv = rsqrtf(var[ri] + 1e-5f);
                    float s = gamma[ri] * inv;
                    scl[im][h] = s;
                    sft[im][h] = (bias[ri] - mean[ri]) * s + beta[ri];
                } else { // EPI 4
                    if (r < 256) {
                        float inv = rsqrtf(var[r] + 1e-5f);
                        float s = gamma[r] * inv;
                        scl[im][h] = s;
                        sft[im][h] = (bias[r] - mean[r]) * s + beta[r];
                    } else {
                        scl[im][h] = 1.f;
                        sft[im][h] = bias2[(r < M) ? (r - 256) : 0];
                    }
                }
            }
    }

    float* D2b = (EPI == 5) ? (D2 + (long)b * d2bs_) : nullptr;

#pragma unroll
    for (int im = 0; im < 2; im++) {
#pragma unroll
        for (int jn = 0; jn < 8; jn++) {
            int c0 = nb + jn * 8 + 2 * qtid;
#pragma unroll
            for (int h = 0; h < 2; h++) {
                int r = mb + im * 16 + qid + h * 8;
                if (r >= M) continue;
                float v0 = acc[im][jn][h * 2 + 0];
                float v1 = acc[im][jn][h * 2 + 1];
                if (EPI == 1) {
                    v0 = fmaxf(v0 * scl[im][h] + sft[im][h], 0.f);
                    v1 = fmaxf(v1 * scl[im][h] + sft[im][h], 0.f);
                }
                if (EPI == 4) {
                    v0 = v0 * scl[im][h] + sft[im][h];
                    v1 = v1 * scl[im][h] + sft[im][h];
                    if (r < 256) { v0 = fmaxf(v0, 0.f); v1 = fmaxf(v1, 0.f); }
                }
                if (EPI == 5) {
#pragma unroll
                    for (int e = 0; e < 2; e++) {
                        int c = c0 + e;
                        float v = e ? v1 : v0;
                        if (c < 256) {
                            v += bias[c];
                            if (ROUND) v = round_tf32f(v);
                            Db[(long)r * ldd + c] = v;
                        } else {
                            int ci = c - 256;
                            float inv = rsqrtf(var[ci] + 1e-5f);
                            float s = gamma[ci] * inv;
                            v = fmaxf(v * s + (bias2[ci] - mean[ci]) * s + beta[ci], 0.f);
                            if (ROUND) v = round_tf32f(v);
                            D2b[(long)r * CT_LD + ci] = v;
                        }
                    }
                    continue;
                }
                if (ROUND) { v0 = round_tf32f(v0); v1 = round_tf32f(v1); }
                if (c0 < N)     Db[(long)r * ldd + c0]     = v0;
                if (c0 + 1 < N) Db[(long)r * ldd + c0 + 1] = v1;
            }
        }
    }
}

// ---------------------------------------------------------------------------
// Row softmax (row length M <= 1024, padded stride ld); stores tf32-rounded.
// ---------------------------------------------------------------------------
__global__ void softmax_rows(float* __restrict__ L, int M, int ld)
{
    float* p = L + (size_t)blockIdx.x * ld;
    const int t = threadIdx.x;

    float r[4];
    float mx = -1e30f;
#pragma unroll
    for (int i = 0; i < 4; i++) {
        int idx = t + i * 256;
        r[i] = (idx < M) ? p[idx] : -1e30f;
        mx = fmaxf(mx, r[i]);
    }
#pragma unroll
    for (int off = 16; off; off >>= 1)
        mx = fmaxf(mx, __shfl_xor_sync(0xffffffffu, mx, off));

    __shared__ float redmax[8];
    __shared__ float redsum[8];
    if ((t & 31) == 0) redmax[t >> 5] = mx;
    __syncthreads();
    mx = redmax[0];
#pragma unroll
    for (int w = 1; w < 8; w++) mx = fmaxf(mx, redmax[w]);

    float s = 0.f;
#pragma unroll
    for (int i = 0; i < 4; i++) {
        int idx = t + i * 256;
        r[i] = (idx < M) ? __expf(r[i] - mx) : 0.f;
        s += r[i];
    }
#pragma unroll
    for (int off = 16; off; off >>= 1)
        s += __shfl_xor_sync(0xffffffffu, s, off);
    if ((t & 31) == 0) redsum[t >> 5] = s;
    __syncthreads();
    s = 0.f;
#pragma unroll
    for (int w = 0; w < 8; w++) s += redsum[w];

    float inv = 1.f / s;
#pragma unroll
    for (int i = 0; i < 4; i++) {
        int idx = t + i * 256;
        if (idx < M) p[idx] = round_tf32f(r[i] * inv);
    }
}

// ---------------------------------------------------------------------------
// xf [B][256][961] -> XF [B][961][256], tf32-rounded. 32x32 tiles, 256 thr.
// ---------------------------------------------------------------------------
__global__ void transpose_round(const float* __restrict__ src, float* __restrict__ dst)
{
    __shared__ float tl[32][33];
    const int b = blockIdx.z;
    const int n0 = blockIdx.x * 32, c0 = blockIdx.y * 32;
    const int tx = threadIdx.x & 31, ty = threadIdx.x >> 5;
    const float* s = src + (size_t)b * 256 * NX;
    float* d = dst + (size_t)b * NX * 256;
#pragma unroll
    for (int i = 0; i < 4; i++) {
        int c = c0 + ty + i * 8, n = n0 + tx;
        tl[ty + i * 8][tx] = (n < NX) ? s[(size_t)c * NX + n] : 0.f;
    }
    __syncthreads();
#pragma unroll
    for (int i = 0; i < 4; i++) {
        int n = n0 + ty + i * 8, c = c0 + tx;
        if (n < NX) d[(size_t)n * 256 + c] = round_tf32f(tl[tx][ty + i * 8]);
    }
}

// ---------------------------------------------------------------------------
// Pre-round weights into g_WR: [Wq | Wg | Ws | Wfi]
// ---------------------------------------------------------------------------
__global__ void round_weights(const float* __restrict__ wq, const float* __restrict__ ws,
                              const float* __restrict__ wg, const float* __restrict__ wfi,
                              float* __restrict__ o)
{
    for (int i = blockIdx.x * 256 + threadIdx.x; i < 393216; i += gridDim.x * 256) {
        float v;
        if      (i < 65536)  v = wq [i];
        else if (i < 131072) v = wg [i - 65536];
        else if (i < 196608) v = ws [i - 131072];
        else                 v = wfi[i - 196608];
        o[i] = round_tf32f(v);
    }
}

// ---------------------------------------------------------------------------
extern "C" void kernel_launch(void* const* d_in, const int* in_sizes, int n_in,
                              void* d_out, int out_size)
{
    const float* zf  = (const float*)d_in[0];
    const float* xf  = (const float*)d_in[1];
    const float* Wq  = (const float*)d_in[2];
    const float* bq  = (const float*)d_in[3];
    const float* Ws_ = (const float*)d_in[4];
    const float* bs  = (const float*)d_in[5];
    const float* Wg  = (const float*)d_in[6];
    const float* bg  = (const float*)d_in[7];
    const float* g_gamma = (const float*)d_in[8];
    const float* g_beta  = (const float*)d_in[9];
    const float* g_mean  = (const float*)d_in[10];
    const float* g_var   = (const float*)d_in[11];
    const float* Wfi = (const float*)d_in[12];
    const float* bfi = (const float*)d_in[13];
    const float* fi_gamma = (const float*)d_in[14];
    const float* fi_beta  = (const float*)d_in[15];
    const float* fi_mean  = (const float*)d_in[16];
    const float* fi_var   = (const float*)d_in[17];
    float* out = (float*)d_out;

    float *XF, *XT, *ZZ, *CT, *PS, *PZ, *WR;
    cudaGetSymbolAddress((void**)&XF, g_XF);
    cudaGetSymbolAddress((void**)&XT, g_XT);
    cudaGetSymbolAddress((void**)&ZZ, g_ZZ);
    cudaGetSymbolAddress((void**)&CT, g_CT);
    cudaGetSymbolAddress((void**)&PS, g_PS);
    cudaGetSymbolAddress((void**)&PZ, g_PZ);
    cudaGetSymbolAddress((void**)&WR, g_WR);

    cudaFuncSetAttribute(mm<0,0,5,true >, cudaFuncAttributeMaxDynamicSharedMemorySize, SMEM_BYTES);
    cudaFuncSetAttribute(mm<0,2,4,true >, cudaFuncAttributeMaxDynamicSharedMemorySize, SMEM_BYTES);
    cudaFuncSetAttribute(mm<0,0,2,false>, cudaFuncAttributeMaxDynamicSharedMemorySize, SMEM_BYTES);
    cudaFuncSetAttribute(mm<0,1,2,false>, cudaFuncAttributeMaxDynamicSharedMemorySize, SMEM_BYTES);
    cudaFuncSetAttribute(mm<0,1,2,true >, cudaFuncAttributeMaxDynamicSharedMemorySize, SMEM_BYTES);
    cudaFuncSetAttribute(mm<0,0,2,true >, cudaFuncAttributeMaxDynamicSharedMemorySize, SMEM_BYTES);
    cudaFuncSetAttribute(mm<0,0,1,false>, cudaFuncAttributeMaxDynamicSharedMemorySize, SMEM_BYTES);

    const long CNZ = (long)C_ * NZ;
    const long XF_BS = (long)NX * 256;
    const long XT_BS = (long)NX * XT_LD;
    const long ZZ_BS = (long)512 * ZZ_LD;
    const long CT_BS = (long)CT_ROWS * CT_LD;
    const long PS_BS = (long)NX * PS_LD;
    const long PZ_BS = (long)NX * PZ_LD;
    const long OUT_BS = (long)256 * NX;
    float* ZTr = ZZ + 256 * ZZ_LD;   // zf_trans rows [256,512)
    float* SE  = CT + 256;           // self_emb cols [256,512)
    float* XGc = CT + 512;           // xf_g cols [512,768)

    // 0) prep: rounded weights; xf^T
    round_weights<<<256, 256>>>(Wq, Ws_, Wg, Wfi, WR);
    transpose_round<<<dim3(31, 8, B_), 256>>>(xf, XF);

    // 1) merged conv: D[n][0:256]=XT(+bq), D2[n][0:256]=xf_g(bn+relu) -> CATT cols 512-767
    mm<0,0,5,true><<<dim3(4, 8, B_), 256, SMEM_BYTES>>>(
        XF, WR, XT, XGc, bq, bg, g_gamma, g_beta, g_mean, g_var,
        NX, 512, 256, 256, 256, XT_LD, XF_BS, 0, XT_BS, CT_BS);
    // 2) ZZ[512][Nz] = [Wg;Ws] @ zf : rows<256 zf_g (bn+relu), rows>=256 zf_trans (+bs)
    mm<0,2,4,true><<<dim3(1, 4, B_), 256, SMEM_BYTES>>>(
        WR + 65536, zf, ZZ, nullptr, bg, bs, g_gamma, g_beta, g_mean, g_var,
        512, NZ, 256, 256, NZ, ZZ_LD, 0, CNZ, ZZ_BS, 0);
    // 3) PS[n][m] = XT @ XT^T
    mm<0,0,2,false><<<dim3(8, 8, B_), 256, SMEM_BYTES>>>(
        XT, XT, PS, nullptr, nullptr, nullptr, nullptr, nullptr, nullptr, nullptr,
        NX, NX, 256, XT_LD, XT_LD, PS_LD, XT_BS, XT_BS, PS_BS, 0);
    // 4) PZ[n][m] = XT @ zf_trans   (B: MODE1 from ZZ rows 256.., src[k=c][m], ld 64)
    mm<0,1,2,false><<<dim3(1, 8, B_), 256, SMEM_BYTES>>>(
        XT, ZTr, PZ, nullptr, nullptr, nullptr, nullptr, nullptr, nullptr, nullptr,
        NX, NZ, 256, XT_LD, ZZ_LD, PZ_LD, XT_BS, ZZ_BS, PZ_BS, 0);
    // 5) softmax
    softmax_rows<<<dim3(B_ * NX), 256>>>(PS, NX, PS_LD);
    softmax_rows<<<dim3(B_ * NX), 256>>>(PZ, NZ, PZ_LD);
    // 6) self_emb[n][c] = PS @ xf_g^T  (A: PS MODE0 K=992; B: MODE1 from CATT+512 ld 768)
    mm<0,1,2,true><<<dim3(2, 8, B_), 256, SMEM_BYTES>>>(
        PS, XGc, SE, nullptr, nullptr, nullptr, nullptr, nullptr, nullptr, nullptr,
        NX, 256, 992, PS_LD, CT_LD, CT_LD, PS_BS, CT_BS, CT_BS, 0);
    // 7) emb[n][c] = PZ @ zf_g^T  (A: PZ MODE0 K=64; B: zf_g MODE0 ld 64)
    mm<0,0,2,true><<<dim3(2, 8, B_), 256, SMEM_BYTES>>>(
        PZ, ZZ, CT, nullptr, nullptr, nullptr, nullptr, nullptr, nullptr, nullptr,
        NX, 256, 64, PZ_LD, ZZ_LD, CT_LD, PZ_BS, ZZ_BS, CT_BS, 0);
    // 8) out[o][n] = relu(bn(Wfi @ CATT^T))  (A: Wfi MODE0 ld 768; B: CATT MODE0 ld 768)
    mm<0,0,1,false><<<dim3(8, 2, B_), 256, SMEM_BYTES>>>(
        WR + 196608, CT, out, nullptr, bfi, nullptr, fi_gamma, fi_beta, fi_mean, fi_var,
        256, NX, 768, 768, CT_LD, NX, 0, CT_BS, OUT_BS, 0);
}